// round 15
// baseline (speedup 1.0000x reference)
#include <cuda_runtime.h>
#include <mma.h>
#include <math.h>

using namespace nvcuda;

#define N_NODES  100000
#define N_EDGES  1600000
#define N_GRAPHS 2048
#define CAP      96          // padded per-node bucket capacity (deg: mean 16, sigma 4)

// ---------------- scratch (device globals; no allocations allowed) ----------
__device__ int   g_cursor[N_NODES];              // bump counters -> in-degree
__device__ int   g_srcs[(size_t)N_NODES * CAP];  // padded per-node src buckets
__device__ float g_dinv[N_NODES];
__device__ float g_A[(size_t)N_NODES * 128];     // h_scaled = (X@W) * dinv[row]
__device__ float g_B[(size_t)N_NODES * 128];     // aggregated output / next input
__device__ float g_pool[N_GRAPHS * 32];

// ---------------- helpers ----------------------------------------------------
__device__ __forceinline__ void red_add_f32x4(float* addr, float4 v) {
    asm volatile("red.global.add.v4.f32 [%0], {%1,%2,%3,%4};"
                 :: "l"(addr), "f"(v.x), "f"(v.y), "f"(v.z), "f"(v.w)
                 : "memory");
}

// ---------------- setup kernels -----------------------------------------------
__global__ void zero_kernel(float* loss_slot) {
    int i = blockIdx.x * blockDim.x + threadIdx.x;
    if (i < N_NODES)       g_cursor[i] = 0;
    if (i < N_GRAPHS * 32) g_pool[i]   = 0.f;
    if (i == 0 && loss_slot) *loss_slot = 0.f;
}

// one pass over edges: bump-allocate into padded per-node buckets
__global__ void fill_kernel(const int* __restrict__ src, const int* __restrict__ dst) {
    int e = blockIdx.x * blockDim.x + threadIdx.x;
    if (e < N_EDGES) {
        int d = dst[e];
        int p = atomicAdd(&g_cursor[d], 1);
        if (p < CAP) g_srcs[(size_t)d * CAP + p] = src[e];
    }
}

__global__ void dinv_kernel() {
    int i = blockIdx.x * blockDim.x + threadIdx.x;
    if (i < N_NODES) g_dinv[i] = rsqrtf((float)g_cursor[i] + 1.0f);
}

// ---------------- GEMM via tf32 tensor cores -----------------------------------
// HS[row,:] = (relu?(X[row,:]) * dinv[row]) @ W   (dinv folded into staged X)
// B fragments hoisted to registers once; next tile's X prefetched during mma.
// NEW: strips interleaved in the k-loop -> STRIPS independent HMMA chains per
// warp (breaks the serial accumulator dependency that capped tensor util).
template<int K, int M, bool RELU_IN, int ROWS>
__global__ void __launch_bounds__(256, 2)
gcn_gemm_tc(const float* __restrict__ X, const float* __restrict__ W,
            float* __restrict__ HS) {
    constexpr int XSTR   = K + 8;
    constexpr int NTILE  = M / 16;              // column tiles (8 / 4 / 2)
    constexpr int RGRP   = 8 / NTILE;           // row groups
    constexpr int STRIPS = ROWS / 16 / RGRP;    // 16-row strips per warp
    constexpr int KS     = K / 8;               // k-steps
    constexpr int PREN   = ROWS * (K / 4) / 256;  // float4 prefetches per thread
    static_assert(STRIPS >= 1, "ROWS too small for RGRP");
    extern __shared__ float smem[];
    float* Ws = smem;                            // K*M
    float* Xs = smem + K * M;                    // ROWS * XSTR

    for (int i = threadIdx.x; i < K * M / 4; i += 256)
        ((float4*)Ws)[i] = __ldg((const float4*)W + i);
    __syncthreads();

    const int warp = threadIdx.x >> 5;
    const int tile = warp % NTILE;
    const int rg   = warp / NTILE;

    // hoist B: load + convert once
    wmma::fragment<wmma::matrix_b, 16, 16, 8, wmma::precision::tf32,
                   wmma::row_major> bf[KS];
    #pragma unroll
    for (int ks = 0; ks < KS; ks++) {
        wmma::load_matrix_sync(bf[ks], Ws + ks * 8 * M + tile * 16, M);
        #pragma unroll
        for (int u = 0; u < bf[ks].num_elements; u++)
            bf[ks].x[u] = wmma::__float_to_tf32(bf[ks].x[u]);
    }

    // register prefetch buffers (X values + per-row dinv)
    float4 pre[PREN];
    float  pdi[PREN];

    auto prefetch = [&](int r0) {
        #pragma unroll
        for (int p = 0; p < PREN; p++) {
            int i  = threadIdx.x + p * 256;
            int rr = i / (K / 4), kk = i % (K / 4);
            int row = r0 + rr;
            if (row < N_NODES) {
                pre[p] = __ldg((const float4*)(X + (size_t)row * K) + kk);
                pdi[p] = __ldg(&g_dinv[row]);
            } else {
                pre[p] = make_float4(0.f, 0.f, 0.f, 0.f);
                pdi[p] = 0.f;
            }
        }
    };

    int row0 = blockIdx.x * ROWS;
    if (row0 < N_NODES) prefetch(row0);

    for (; row0 < N_NODES; row0 += gridDim.x * ROWS) {
        __syncthreads();   // previous tile's compute done reading Xs
        #pragma unroll
        for (int p = 0; p < PREN; p++) {
            int i  = threadIdx.x + p * 256;
            int rr = i / (K / 4), kk = i % (K / 4);
            float4 v = pre[p];
            if (RELU_IN) {
                v.x = fmaxf(v.x, 0.f); v.y = fmaxf(v.y, 0.f);
                v.z = fmaxf(v.z, 0.f); v.w = fmaxf(v.w, 0.f);
            }
            float di = pdi[p];
            v.x *= di; v.y *= di; v.z *= di; v.w *= di;
            *(float4*)(Xs + rr * XSTR + kk * 4) = v;
        }
        __syncthreads();   // Xs ready

        // prefetch next tile's X while this tile computes
        int nxt = row0 + gridDim.x * ROWS;
        if (nxt < N_NODES) prefetch(nxt);

        // STRIPS independent accumulator chains, interleaved in the k-loop
        wmma::fragment<wmma::accumulator, 16, 16, 8, float> acc[STRIPS];
        #pragma unroll
        for (int st = 0; st < STRIPS; st++) wmma::fill_fragment(acc[st], 0.f);

        #pragma unroll
        for (int ks = 0; ks < KS; ks++) {
            #pragma unroll
            for (int st = 0; st < STRIPS; st++) {
                int rloc = (rg * STRIPS + st) * 16;
                wmma::fragment<wmma::matrix_a, 16, 16, 8, wmma::precision::tf32,
                               wmma::row_major> a;
                wmma::load_matrix_sync(a, Xs + rloc * XSTR + ks * 8, XSTR);
                #pragma unroll
                for (int t = 0; t < a.num_elements; t++)
                    a.x[t] = wmma::__float_to_tf32(a.x[t]);
                wmma::mma_sync(acc[st], a, bf[ks], acc[st]);
            }
        }

        #pragma unroll
        for (int st = 0; st < STRIPS; st++) {
            int rbase = row0 + (rg * STRIPS + st) * 16;
            if (rbase < N_NODES)   // N_NODES % 16 == 0 -> strip fully in-bounds
                wmma::store_matrix_sync(HS + (size_t)rbase * M + tile * 16,
                                        acc[st], M, wmma::mem_row_major);
        }
    }
}

// ---------------- aggregation: OUT[v] = dinv[v]*(sum_in HS[s] + HS[v]) + b ----
// R11 form (x2 accumulator chains) — frozen; deeper unrolls regress (R5/R13).
template<int F>
__global__ void agg_gather(const float* __restrict__ HS, const float* __restrict__ bias,
                           float* __restrict__ OUT) {
    constexpr int TPN = F / 4;
    unsigned gid = blockIdx.x * blockDim.x + threadIdx.x;
    unsigned v = gid / TPN;
    if (v >= N_NODES) return;
    unsigned c = gid % TPN;
    const float4* hs = (const float4*)HS;

    const int* seg = g_srcs + (size_t)v * CAP;
    int cnt = __ldg(&g_cursor[v]);
    cnt = (cnt < CAP) ? cnt : CAP;

    float4 acc0 = __ldg(hs + (size_t)v * TPN + c);       // self-loop term
    float4 acc1 = make_float4(0.f, 0.f, 0.f, 0.f);

    int i = 0;
    for (; i + 1 < cnt; i += 2) {
        int s0 = __ldg(&seg[i]);
        int s1 = __ldg(&seg[i + 1]);
        float4 m0 = __ldg(hs + (size_t)s0 * TPN + c);
        float4 m1 = __ldg(hs + (size_t)s1 * TPN + c);
        acc0.x += m0.x; acc0.y += m0.y; acc0.z += m0.z; acc0.w += m0.w;
        acc1.x += m1.x; acc1.y += m1.y; acc1.z += m1.z; acc1.w += m1.w;
    }
    if (i < cnt) {
        int s = __ldg(&seg[i]);
        float4 m = __ldg(hs + (size_t)s * TPN + c);
        acc0.x += m.x; acc0.y += m.y; acc0.z += m.z; acc0.w += m.w;
    }

    float di = __ldg(&g_dinv[v]);
    float4 bb = __ldg((const float4*)bias + c);
    float4 o;
    o.x = fmaf(acc0.x + acc1.x, di, bb.x);
    o.y = fmaf(acc0.y + acc1.y, di, bb.y);
    o.z = fmaf(acc0.z + acc1.z, di, bb.z);
    o.w = fmaf(acc0.w + acc1.w, di, bb.w);
    ((float4*)OUT)[(size_t)v * TPN + c] = o;
}

// ---------------- layer-3 aggregation fused with pooling (F=32) ----------------
__global__ void agg_pool(const float* __restrict__ HS, const float* __restrict__ bias,
                         const int* __restrict__ batch) {
    constexpr int TPN = 8;
    unsigned gid = blockIdx.x * blockDim.x + threadIdx.x;
    unsigned v = gid / TPN;
    if (v >= N_NODES) return;
    unsigned c = gid % TPN;
    const float4* hs = (const float4*)HS;

    const int* seg = g_srcs + (size_t)v * CAP;
    int cnt = __ldg(&g_cursor[v]);
    cnt = (cnt < CAP) ? cnt : CAP;

    float4 acc0 = __ldg(hs + (size_t)v * TPN + c);
    float4 acc1 = make_float4(0.f, 0.f, 0.f, 0.f);

    int i = 0;
    for (; i + 1 < cnt; i += 2) {
        int s0 = __ldg(&seg[i]);
        int s1 = __ldg(&seg[i + 1]);
        float4 m0 = __ldg(hs + (size_t)s0 * TPN + c);
        float4 m1 = __ldg(hs + (size_t)s1 * TPN + c);
        acc0.x += m0.x; acc0.y += m0.y; acc0.z += m0.z; acc0.w += m0.w;
        acc1.x += m1.x; acc1.y += m1.y; acc1.z += m1.z; acc1.w += m1.w;
    }
    if (i < cnt) {
        int s = __ldg(&seg[i]);
        float4 m = __ldg(hs + (size_t)s * TPN + c);
        acc0.x += m.x; acc0.y += m.y; acc0.z += m.z; acc0.w += m.w;
    }

    float di = __ldg(&g_dinv[v]);
    float4 bb = __ldg((const float4*)bias + c);
    float4 o;
    o.x = fmaf(acc0.x + acc1.x, di, bb.x);
    o.y = fmaf(acc0.y + acc1.y, di, bb.y);
    o.z = fmaf(acc0.z + acc1.z, di, bb.z);
    o.w = fmaf(acc0.w + acc1.w, di, bb.w);

    int g = __ldg(&batch[v]);
    red_add_f32x4(&g_pool[g * 32 + c * 4], o);
}

// ---------------- head: counts via binary search on sorted batch ---------------
__device__ __forceinline__ int lower_bound_batch(const int* __restrict__ batch, int key) {
    int lo = 0, hi = N_NODES;
    while (lo < hi) {
        int mid = (lo + hi) >> 1;
        if (__ldg(&batch[mid]) < key) lo = mid + 1; else hi = mid;
    }
    return lo;
}

__global__ void head_kernel(const float* __restrict__ Wl, const float* __restrict__ bl,
                            const int* __restrict__ targets, const int* __restrict__ batch,
                            float* __restrict__ out, int out_size) {
    int g = blockIdx.x * blockDim.x + threadIdx.x;
    float loss = 0.f;
    if (g < N_GRAPHS) {
        int s0 = lower_bound_batch(batch, g);
        int s1 = lower_bound_batch(batch, g + 1);
        float cnt = (float)(s1 - s0);
        float inv = 1.0f / fmaxf(cnt, 1.0f);
        float acc = 0.f;
        #pragma unroll
        for (int j = 0; j < 32; j++)
            acc += g_pool[g * 32 + j] * inv * __ldg(&Wl[j]);
        float l = acc + __ldg(&bl[0]);
        out[g] = 1.0f / (1.0f + expf(-l));
        float y = (float)__ldg(&targets[g]);
        loss = fmaxf(l, 0.f) - l * y + log1pf(expf(-fabsf(l)));
    }
    __shared__ float red[256];
    red[threadIdx.x] = loss;
    __syncthreads();
    for (int s = 128; s > 0; s >>= 1) {
        if (threadIdx.x < s) red[threadIdx.x] += red[threadIdx.x + s];
        __syncthreads();
    }
    if (threadIdx.x == 0 && out_size > N_GRAPHS)
        atomicAdd(&out[N_GRAPHS], red[0] * (1.0f / N_GRAPHS));
}

// ---------------- launch ------------------------------------------------------
extern "C" void kernel_launch(void* const* d_in, const int* in_sizes, int n_in,
                              void* d_out, int out_size) {
    const float* x       = (const float*)d_in[0];
    const int*   eidx    = (const int*)  d_in[1];
    const int*   batch   = (const int*)  d_in[2];
    const int*   targets = (const int*)  d_in[3];
    const float* W1 = (const float*)d_in[4];
    const float* b1 = (const float*)d_in[5];
    const float* W2 = (const float*)d_in[6];
    const float* b2 = (const float*)d_in[7];
    const float* W3 = (const float*)d_in[8];
    const float* b3 = (const float*)d_in[9];
    const float* Wl = (const float*)d_in[10];
    const float* bl = (const float*)d_in[11];
    float* out = (float*)d_out;

    const int* src = eidx;
    const int* dst = eidx + N_EDGES;

    float* A;  cudaGetSymbolAddress((void**)&A, g_A);
    float* B;  cudaGetSymbolAddress((void**)&B, g_B);

    const int smem1 = 128 * 128 * 4 + 32 * 136 * 4;  // 82944
    const int smem2 = 128 * 64  * 4 + 32 * 136 * 4;  // 50176
    const int smem3 = 64  * 32  * 4 + 64 * 72  * 4;  // 26624
    cudaFuncSetAttribute(gcn_gemm_tc<128,128,false,32>,
                         cudaFuncAttributeMaxDynamicSharedMemorySize, smem1);
    cudaFuncSetAttribute(gcn_gemm_tc<128,64,true,32>,
                         cudaFuncAttributeMaxDynamicSharedMemorySize, smem2);
    cudaFuncSetAttribute(gcn_gemm_tc<64,32,true,64>,
                         cudaFuncAttributeMaxDynamicSharedMemorySize, smem3);

    float* loss_slot = (out_size > N_GRAPHS) ? (out + N_GRAPHS) : nullptr;

    // ---- setup: zero -> fill (padded buckets) -> dinv
    zero_kernel<<<(N_NODES + 255) / 256, 256>>>(loss_slot);
    fill_kernel<<<(N_EDGES + 255) / 256, 256>>>(src, dst);
    dinv_kernel<<<(N_NODES + 255) / 256, 256>>>();

    // ---- layer 1: 128 -> 128   (gemm1 is launch #4 -> ncu window)
    gcn_gemm_tc<128,128,false,32><<<296, 256, smem1>>>(x, W1, A);
    agg_gather<128><<<((unsigned)N_NODES * 32 + 255) / 256, 256>>>(A, b1, B);
    // ---- layer 2: 128 -> 64 (relu on input)
    gcn_gemm_tc<128,64,true,32><<<296, 256, smem2>>>(B, W2, A);
    agg_gather<64><<<((unsigned)N_NODES * 16 + 255) / 256, 256>>>(A, b2, B);
    // ---- layer 3: 64 -> 32 (relu on input), aggregation fused with pooling
    gcn_gemm_tc<64,32,true,64><<<296, 256, smem3>>>(B, W3, A);
    agg_pool<<<((unsigned)N_NODES * 8 + 255) / 256, 256>>>(A, b3, batch);

    // ---- head
    head_kernel<<<(N_GRAPHS + 255) / 256, 256>>>(Wl, bl, targets, batch, out, out_size);
}

// round 16
// speedup vs baseline: 1.2054x; 1.2054x over previous
#include <cuda_runtime.h>
#include <cuda_bf16.h>
#include <mma.h>
#include <math.h>

using namespace nvcuda;

#define N_NODES  100000
#define N_EDGES  1600000
#define N_GRAPHS 2048
#define CAP      96          // padded per-node bucket capacity (deg: mean 16, sigma 4)

// ---------------- scratch (device globals; no allocations allowed) ----------
__device__ int   g_cursor[N_NODES];              // bump counters -> in-degree
__device__ int   g_srcs[(size_t)N_NODES * CAP];  // padded per-node src buckets
__device__ float g_dinv[N_NODES];
__device__ float g_A[(size_t)N_NODES * 128];     // h_scaled = (X@W) * dinv[row]
__device__ float g_B[(size_t)N_NODES * 128];     // aggregated output / next input
__device__ float g_pool[N_GRAPHS * 32];

// ---------------- helpers ----------------------------------------------------
__device__ __forceinline__ void red_add_f32x4(float* addr, float4 v) {
    asm volatile("red.global.add.v4.f32 [%0], {%1,%2,%3,%4};"
                 :: "l"(addr), "f"(v.x), "f"(v.y), "f"(v.z), "f"(v.w)
                 : "memory");
}

// ---------------- setup kernels -----------------------------------------------
__global__ void zero_kernel(float* loss_slot) {
    int i = blockIdx.x * blockDim.x + threadIdx.x;
    if (i < N_NODES)       g_cursor[i] = 0;
    if (i < N_GRAPHS * 32) g_pool[i]   = 0.f;
    if (i == 0 && loss_slot) *loss_slot = 0.f;
}

// one pass over edges: bump-allocate into padded per-node buckets
__global__ void fill_kernel(const int* __restrict__ src, const int* __restrict__ dst) {
    int e = blockIdx.x * blockDim.x + threadIdx.x;
    if (e < N_EDGES) {
        int d = dst[e];
        int p = atomicAdd(&g_cursor[d], 1);
        if (p < CAP) g_srcs[(size_t)d * CAP + p] = src[e];
    }
}

__global__ void dinv_kernel() {
    int i = blockIdx.x * blockDim.x + threadIdx.x;
    if (i < N_NODES) g_dinv[i] = rsqrtf((float)g_cursor[i] + 1.0f);
}

// ---------------- GEMM via bf16 tensor cores (m16n16k16) ----------------------
// HS[row,:] = (relu?(X[row,:]) * dinv[row]) @ W   (dinv folded into staged X)
// X and W converted to bf16 once at staging; B fragments hoisted to registers;
// next tile's X prefetched during mma; strips interleaved (independent chains).
template<int K, int M, bool RELU_IN, int ROWS>
__global__ void __launch_bounds__(256, 2)
gcn_gemm_tc(const float* __restrict__ X, const float* __restrict__ W,
            float* __restrict__ HS) {
    constexpr int XSTR   = K + 16;              // bf16 elements (32B pad)
    constexpr int NTILE  = M / 16;              // column tiles (8 / 4 / 2)
    constexpr int RGRP   = 8 / NTILE;           // row groups
    constexpr int STRIPS = ROWS / 16 / RGRP;    // 16-row strips per warp
    constexpr int KS     = K / 16;              // k-steps (bf16: 16 per mma)
    constexpr int PREN   = ROWS * (K / 4) / 256;  // float4 prefetches per thread
    static_assert(STRIPS >= 1, "ROWS too small for RGRP");
    extern __shared__ __nv_bfloat16 smem_b[];
    __nv_bfloat16* Ws = smem_b;                  // K*M bf16
    __nv_bfloat16* Xs = smem_b + K * M;          // ROWS * XSTR bf16

    for (int i = threadIdx.x; i < K * M / 4; i += 256) {
        float4 w = __ldg((const float4*)W + i);
        __nv_bfloat162 lo = __floats2bfloat162_rn(w.x, w.y);
        __nv_bfloat162 hi = __floats2bfloat162_rn(w.z, w.w);
        uint2 u;
        u.x = *(unsigned*)&lo;
        u.y = *(unsigned*)&hi;
        *(uint2*)(Ws + i * 4) = u;
    }
    __syncthreads();

    const int warp = threadIdx.x >> 5;
    const int tile = warp % NTILE;
    const int rg   = warp / NTILE;

    // hoist B fragments: load once (bf16, no further conversion)
    wmma::fragment<wmma::matrix_b, 16, 16, 16, __nv_bfloat16,
                   wmma::row_major> bf[KS];
    #pragma unroll
    for (int ks = 0; ks < KS; ks++)
        wmma::load_matrix_sync(bf[ks], Ws + ks * 16 * M + tile * 16, M);

    // register prefetch buffers (X values + per-row dinv)
    float4 pre[PREN];
    float  pdi[PREN];

    auto prefetch = [&](int r0) {
        #pragma unroll
        for (int p = 0; p < PREN; p++) {
            int i  = threadIdx.x + p * 256;
            int rr = i / (K / 4), kk = i % (K / 4);
            int row = r0 + rr;
            if (row < N_NODES) {
                pre[p] = __ldg((const float4*)(X + (size_t)row * K) + kk);
                pdi[p] = __ldg(&g_dinv[row]);
            } else {
                pre[p] = make_float4(0.f, 0.f, 0.f, 0.f);
                pdi[p] = 0.f;
            }
        }
    };

    int row0 = blockIdx.x * ROWS;
    if (row0 < N_NODES) prefetch(row0);

    for (; row0 < N_NODES; row0 += gridDim.x * ROWS) {
        __syncthreads();   // previous tile's compute done reading Xs
        #pragma unroll
        for (int p = 0; p < PREN; p++) {
            int i  = threadIdx.x + p * 256;
            int rr = i / (K / 4), kk = i % (K / 4);
            float4 v = pre[p];
            if (RELU_IN) {
                v.x = fmaxf(v.x, 0.f); v.y = fmaxf(v.y, 0.f);
                v.z = fmaxf(v.z, 0.f); v.w = fmaxf(v.w, 0.f);
            }
            float di = pdi[p];
            __nv_bfloat162 lo = __floats2bfloat162_rn(v.x * di, v.y * di);
            __nv_bfloat162 hi = __floats2bfloat162_rn(v.z * di, v.w * di);
            uint2 u;
            u.x = *(unsigned*)&lo;
            u.y = *(unsigned*)&hi;
            *(uint2*)(Xs + rr * XSTR + kk * 4) = u;
        }
        __syncthreads();   // Xs ready

        // prefetch next tile's X while this tile computes
        int nxt = row0 + gridDim.x * ROWS;
        if (nxt < N_NODES) prefetch(nxt);

        // STRIPS independent accumulator chains, interleaved in the k-loop
        wmma::fragment<wmma::accumulator, 16, 16, 16, float> acc[STRIPS];
        #pragma unroll
        for (int st = 0; st < STRIPS; st++) wmma::fill_fragment(acc[st], 0.f);

        #pragma unroll
        for (int ks = 0; ks < KS; ks++) {
            #pragma unroll
            for (int st = 0; st < STRIPS; st++) {
                int rloc = (rg * STRIPS + st) * 16;
                wmma::fragment<wmma::matrix_a, 16, 16, 16, __nv_bfloat16,
                               wmma::row_major> a;
                wmma::load_matrix_sync(a, Xs + rloc * XSTR + ks * 16, XSTR);
                wmma::mma_sync(acc[st], a, bf[ks], acc[st]);
            }
        }

        #pragma unroll
        for (int st = 0; st < STRIPS; st++) {
            int rbase = row0 + (rg * STRIPS + st) * 16;
            if (rbase < N_NODES)   // N_NODES % 16 == 0 -> strip fully in-bounds
                wmma::store_matrix_sync(HS + (size_t)rbase * M + tile * 16,
                                        acc[st], M, wmma::mem_row_major);
        }
    }
}

// ---------------- aggregation: OUT[v] = dinv[v]*(sum_in HS[s] + HS[v]) + b ----
// R11 form (x2 accumulator chains) — frozen; deeper unrolls regress (R5/R13).
template<int F>
__global__ void agg_gather(const float* __restrict__ HS, const float* __restrict__ bias,
                           float* __restrict__ OUT) {
    constexpr int TPN = F / 4;
    unsigned gid = blockIdx.x * blockDim.x + threadIdx.x;
    unsigned v = gid / TPN;
    if (v >= N_NODES) return;
    unsigned c = gid % TPN;
    const float4* hs = (const float4*)HS;

    const int* seg = g_srcs + (size_t)v * CAP;
    int cnt = __ldg(&g_cursor[v]);
    cnt = (cnt < CAP) ? cnt : CAP;

    float4 acc0 = __ldg(hs + (size_t)v * TPN + c);       // self-loop term
    float4 acc1 = make_float4(0.f, 0.f, 0.f, 0.f);

    int i = 0;
    for (; i + 1 < cnt; i += 2) {
        int s0 = __ldg(&seg[i]);
        int s1 = __ldg(&seg[i + 1]);
        float4 m0 = __ldg(hs + (size_t)s0 * TPN + c);
        float4 m1 = __ldg(hs + (size_t)s1 * TPN + c);
        acc0.x += m0.x; acc0.y += m0.y; acc0.z += m0.z; acc0.w += m0.w;
        acc1.x += m1.x; acc1.y += m1.y; acc1.z += m1.z; acc1.w += m1.w;
    }
    if (i < cnt) {
        int s = __ldg(&seg[i]);
        float4 m = __ldg(hs + (size_t)s * TPN + c);
        acc0.x += m.x; acc0.y += m.y; acc0.z += m.z; acc0.w += m.w;
    }

    float di = __ldg(&g_dinv[v]);
    float4 bb = __ldg((const float4*)bias + c);
    float4 o;
    o.x = fmaf(acc0.x + acc1.x, di, bb.x);
    o.y = fmaf(acc0.y + acc1.y, di, bb.y);
    o.z = fmaf(acc0.z + acc1.z, di, bb.z);
    o.w = fmaf(acc0.w + acc1.w, di, bb.w);
    ((float4*)OUT)[(size_t)v * TPN + c] = o;
}

// ---------------- layer-3 aggregation fused with pooling (F=32) ----------------
__global__ void agg_pool(const float* __restrict__ HS, const float* __restrict__ bias,
                         const int* __restrict__ batch) {
    constexpr int TPN = 8;
    unsigned gid = blockIdx.x * blockDim.x + threadIdx.x;
    unsigned v = gid / TPN;
    if (v >= N_NODES) return;
    unsigned c = gid % TPN;
    const float4* hs = (const float4*)HS;

    const int* seg = g_srcs + (size_t)v * CAP;
    int cnt = __ldg(&g_cursor[v]);
    cnt = (cnt < CAP) ? cnt : CAP;

    float4 acc0 = __ldg(hs + (size_t)v * TPN + c);
    float4 acc1 = make_float4(0.f, 0.f, 0.f, 0.f);

    int i = 0;
    for (; i + 1 < cnt; i += 2) {
        int s0 = __ldg(&seg[i]);
        int s1 = __ldg(&seg[i + 1]);
        float4 m0 = __ldg(hs + (size_t)s0 * TPN + c);
        float4 m1 = __ldg(hs + (size_t)s1 * TPN + c);
        acc0.x += m0.x; acc0.y += m0.y; acc0.z += m0.z; acc0.w += m0.w;
        acc1.x += m1.x; acc1.y += m1.y; acc1.z += m1.z; acc1.w += m1.w;
    }
    if (i < cnt) {
        int s = __ldg(&seg[i]);
        float4 m = __ldg(hs + (size_t)s * TPN + c);
        acc0.x += m.x; acc0.y += m.y; acc0.z += m.z; acc0.w += m.w;
    }

    float di = __ldg(&g_dinv[v]);
    float4 bb = __ldg((const float4*)bias + c);
    float4 o;
    o.x = fmaf(acc0.x + acc1.x, di, bb.x);
    o.y = fmaf(acc0.y + acc1.y, di, bb.y);
    o.z = fmaf(acc0.z + acc1.z, di, bb.z);
    o.w = fmaf(acc0.w + acc1.w, di, bb.w);

    int g = __ldg(&batch[v]);
    red_add_f32x4(&g_pool[g * 32 + c * 4], o);
}

// ---------------- head: counts via binary search on sorted batch ---------------
__device__ __forceinline__ int lower_bound_batch(const int* __restrict__ batch, int key) {
    int lo = 0, hi = N_NODES;
    while (lo < hi) {
        int mid = (lo + hi) >> 1;
        if (__ldg(&batch[mid]) < key) lo = mid + 1; else hi = mid;
    }
    return lo;
}

__global__ void head_kernel(const float* __restrict__ Wl, const float* __restrict__ bl,
                            const int* __restrict__ targets, const int* __restrict__ batch,
                            float* __restrict__ out, int out_size) {
    int g = blockIdx.x * blockDim.x + threadIdx.x;
    float loss = 0.f;
    if (g < N_GRAPHS) {
        int s0 = lower_bound_batch(batch, g);
        int s1 = lower_bound_batch(batch, g + 1);
        float cnt = (float)(s1 - s0);
        float inv = 1.0f / fmaxf(cnt, 1.0f);
        float acc = 0.f;
        #pragma unroll
        for (int j = 0; j < 32; j++)
            acc += g_pool[g * 32 + j] * inv * __ldg(&Wl[j]);
        float l = acc + __ldg(&bl[0]);
        out[g] = 1.0f / (1.0f + expf(-l));
        float y = (float)__ldg(&targets[g]);
        loss = fmaxf(l, 0.f) - l * y + log1pf(expf(-fabsf(l)));
    }
    __shared__ float red[256];
    red[threadIdx.x] = loss;
    __syncthreads();
    for (int s = 128; s > 0; s >>= 1) {
        if (threadIdx.x < s) red[threadIdx.x] += red[threadIdx.x + s];
        __syncthreads();
    }
    if (threadIdx.x == 0 && out_size > N_GRAPHS)
        atomicAdd(&out[N_GRAPHS], red[0] * (1.0f / N_GRAPHS));
}

// ---------------- launch ------------------------------------------------------
extern "C" void kernel_launch(void* const* d_in, const int* in_sizes, int n_in,
                              void* d_out, int out_size) {
    const float* x       = (const float*)d_in[0];
    const int*   eidx    = (const int*)  d_in[1];
    const int*   batch   = (const int*)  d_in[2];
    const int*   targets = (const int*)  d_in[3];
    const float* W1 = (const float*)d_in[4];
    const float* b1 = (const float*)d_in[5];
    const float* W2 = (const float*)d_in[6];
    const float* b2 = (const float*)d_in[7];
    const float* W3 = (const float*)d_in[8];
    const float* b3 = (const float*)d_in[9];
    const float* Wl = (const float*)d_in[10];
    const float* bl = (const float*)d_in[11];
    float* out = (float*)d_out;

    const int* src = eidx;
    const int* dst = eidx + N_EDGES;

    float* A;  cudaGetSymbolAddress((void**)&A, g_A);
    float* B;  cudaGetSymbolAddress((void**)&B, g_B);

    // bf16 smem: (K*M + ROWS*(K+16)) * 2 bytes
    const int smem1 = (128 * 128 + 32 * 144) * 2;  // 41984
    const int smem2 = (128 * 64  + 32 * 144) * 2;  // 25600
    const int smem3 = (64  * 32  + 64 * 80 ) * 2;  // 14336
    cudaFuncSetAttribute(gcn_gemm_tc<128,128,false,32>,
                         cudaFuncAttributeMaxDynamicSharedMemorySize, smem1);
    cudaFuncSetAttribute(gcn_gemm_tc<128,64,true,32>,
                         cudaFuncAttributeMaxDynamicSharedMemorySize, smem2);
    cudaFuncSetAttribute(gcn_gemm_tc<64,32,true,64>,
                         cudaFuncAttributeMaxDynamicSharedMemorySize, smem3);

    float* loss_slot = (out_size > N_GRAPHS) ? (out + N_GRAPHS) : nullptr;

    // ---- setup: zero -> fill (padded buckets) -> dinv
    zero_kernel<<<(N_NODES + 255) / 256, 256>>>(loss_slot);
    fill_kernel<<<(N_EDGES + 255) / 256, 256>>>(src, dst);
    dinv_kernel<<<(N_NODES + 255) / 256, 256>>>();

    // ---- layer 1: 128 -> 128   (gemm1 is launch #4 -> ncu window)
    gcn_gemm_tc<128,128,false,32><<<296, 256, smem1>>>(x, W1, A);
    agg_gather<128><<<((unsigned)N_NODES * 32 + 255) / 256, 256>>>(A, b1, B);
    // ---- layer 2: 128 -> 64 (relu on input)
    gcn_gemm_tc<128,64,true,32><<<296, 256, smem2>>>(B, W2, A);
    agg_gather<64><<<((unsigned)N_NODES * 16 + 255) / 256, 256>>>(A, b2, B);
    // ---- layer 3: 64 -> 32 (relu on input), aggregation fused with pooling
    gcn_gemm_tc<64,32,true,64><<<296, 256, smem3>>>(B, W3, A);
    agg_pool<<<((unsigned)N_NODES * 8 + 255) / 256, 256>>>(A, b3, batch);

    // ---- head
    head_kernel<<<(N_GRAPHS + 255) / 256, 256>>>(Wl, bl, targets, batch, out, out_size);
}